// round 4
// baseline (speedup 1.0000x reference)
#include <cuda_runtime.h>

// EM_rec_loss: fully fused single-kernel loss on GB300.
// float2-per-thread layout: low register pressure -> 6 blocks/SM occupancy.
//
// Inputs (metadata order):
//   d_in[0] segmentations   [8,4,7,128,128]   f32
//   d_in[1] masks           [8,4,7,128,128]   f32
//   d_in[2] reconstructions [8,4,7,3,128,128] f32
//   d_in[3] rec_tgt         [8,4,3,128,128]   f32
//   d_in[4] masks_vis       [8,4,7,128,128]   f32
//   d_in[5] attn_index      [8,4,7,7]         f32
// Output: scalar f32.

#define NB 7
#define NS 7
#define HH 128
#define WW 128
#define HW (HH * WW)        // 16384
#define HW2 (HW / 2)        // 8192 float2 groups per image plane
#define NIMG 32             // b*f
#define TPB 256
#define NWARP (TPB / 32)    // 8
#define BPN (HW2 / TPB)     // 32 blocks per image
#define GRID (NIMG * BPN)   // 1024 blocks

__device__ float        g_part[GRID];
__device__ unsigned int g_cnt = 0;   // wraps to 0 every full grid -> graph-replay safe

__device__ __forceinline__ float warp_sum(float v) {
    // Fixed butterfly order -> deterministic.
    #pragma unroll
    for (int m = 16; m > 0; m >>= 1)
        v += __shfl_xor_sync(0xFFFFFFFFu, v, m);
    return v;
}

__global__ __launch_bounds__(TPB, 6) void loss_main(
    const float* __restrict__ seg,
    const float* __restrict__ masks,
    const float* __restrict__ rec,
    const float* __restrict__ tgt,
    const float* __restrict__ mvis,
    const float* __restrict__ ai,
    float* __restrict__ out)
{
    __shared__ float s_aib[NS * NB];  // ai * (1/HW)  (BCE weight)
    __shared__ float s_aim[NS * NB];  // ai * 0.1     (MSE weight)
    __shared__ float s_asum[NB];      // sum_s ai*(1/HW)
    __shared__ float s_wred[NWARP];
    __shared__ int   s_last;

    const int n = blockIdx.x / BPN;
    const int t = threadIdx.x;

    if (t < NS * NB) {
        float a = ai[n * NS * NB + t];
        s_aib[t] = a * (1.0f / (float)HW);
        s_aim[t] = a * 0.1f;
    }
    __syncthreads();
    if (t < NB) {
        float s = 0.0f;
        #pragma unroll
        for (int j = 0; j < NS; j++) s += s_aib[j * NB + t];
        s_asum[t] = s;
    }
    __syncthreads();

    const int p2 = (blockIdx.x % BPN) * TPB + t;  // float2 index within one plane

    const float2* __restrict__ seg2 = (const float2*)seg;
    const float2* __restrict__ mk2  = (const float2*)masks;
    const float2* __restrict__ rc2  = (const float2*)rec;
    const float2* __restrict__ tg2  = (const float2*)tgt;
    const float2* __restrict__ mv2  = (const float2*)mvis;

    float acc0 = 0.0f, acc1 = 0.0f;

    // ================= Phase 1: BCE (masks -> wm, then seg logs) =============
    {
        float wm[NB][2];
        #pragma unroll
        for (int b = 0; b < NB; b++) { wm[b][0] = 0.0f; wm[b][1] = 0.0f; }

        #pragma unroll
        for (int s = 0; s < NS; s++) {
            float2 mk = mk2[(size_t)(n * NS + s) * HW2 + p2];
            float mb0 = mk.x > 0.5f ? 1.0f : 0.0f;
            float mb1 = mk.y > 0.5f ? 1.0f : 0.0f;
            #pragma unroll
            for (int b = 0; b < NB; b++) {
                float ab = s_aib[s * NB + b];
                wm[b][0] = fmaf(mb0, ab, wm[b][0]);
                wm[b][1] = fmaf(mb1, ab, wm[b][1]);
            }
        }

        #pragma unroll
        for (int b = 0; b < NB; b++) {
            float2 sg = seg2[(size_t)(n * NB + b) * HW2 + p2];
            float asb = s_asum[b];
            float lp0  = fmaxf(__logf(sg.x), -100.0f);
            float l1p0 = fmaxf(__logf(1.0f - sg.x), -100.0f);
            acc0 = fmaf(-l1p0, asb, acc0);
            acc0 = fmaf(l1p0 - lp0, wm[b][0], acc0);
            float lp1  = fmaxf(__logf(sg.y), -100.0f);
            float l1p1 = fmaxf(__logf(1.0f - sg.y), -100.0f);
            acc1 = fmaf(-l1p1, asb, acc1);
            acc1 = fmaf(l1p1 - lp1, wm[b][1], acc1);
        }
    }

    // ================= Phase 2: MSE (mvis -> wmv, then rec/tgt) ==============
    {
        float wmv[NB][2];
        #pragma unroll
        for (int b = 0; b < NB; b++) { wmv[b][0] = 0.0f; wmv[b][1] = 0.0f; }

        #pragma unroll
        for (int s = 0; s < NS; s++) {
            float2 mv = mv2[(size_t)(n * NS + s) * HW2 + p2];
            float vb0 = mv.x > 0.5f ? 1.0f : 0.0f;
            float vb1 = mv.y > 0.5f ? 1.0f : 0.0f;
            #pragma unroll
            for (int b = 0; b < NB; b++) {
                float am = s_aim[s * NB + b];
                wmv[b][0] = fmaf(vb0, am, wmv[b][0]);
                wmv[b][1] = fmaf(vb1, am, wmv[b][1]);
            }
        }

        float2 t0 = tg2[((size_t)n * 3 + 0) * HW2 + p2];
        float2 t1 = tg2[((size_t)n * 3 + 1) * HW2 + p2];
        float2 t2 = tg2[((size_t)n * 3 + 2) * HW2 + p2];

        #pragma unroll
        for (int b = 0; b < NB; b++) {
            float2 r0 = rc2[((size_t)(n * NB + b) * 3 + 0) * HW2 + p2];
            float2 r1 = rc2[((size_t)(n * NB + b) * 3 + 1) * HW2 + p2];
            float2 r2 = rc2[((size_t)(n * NB + b) * 3 + 2) * HW2 + p2];

            float d0 = r0.x - t0.x;
            float d1 = r1.x - t1.x;
            float d2 = r2.x - t2.x;
            float e0 = fmaf(d0, d0, fmaf(d1, d1, d2 * d2));
            acc0 = fmaf(e0, wmv[b][0], acc0);

            float e0y = r0.y - t0.y;
            float e1y = r1.y - t1.y;
            float e2y = r2.y - t2.y;
            float e1 = fmaf(e0y, e0y, fmaf(e1y, e1y, e2y * e2y));
            acc1 = fmaf(e1, wmv[b][1], acc1);
        }
    }

    float total = acc0 + acc1;

    // Deterministic block reduction: warp shuffle + tiny smem stage.
    total = warp_sum(total);
    const int lane = t & 31;
    const int warp = t >> 5;
    if (lane == 0) s_wred[warp] = total;
    __syncthreads();
    if (warp == 0) {
        float v = (lane < NWARP) ? s_wred[lane] : 0.0f;
        #pragma unroll
        for (int m = NWARP / 2; m > 0; m >>= 1)
            v += __shfl_xor_sync(0xFFFFFFFFu, v, m);
        if (lane == 0) {
            g_part[blockIdx.x] = v;
            __threadfence();
            unsigned int old = atomicInc(&g_cnt, GRID - 1);  // wraps to 0 -> replay-safe
            s_last = (old == GRID - 1) ? 1 : 0;
        }
    }
    __syncthreads();

    if (s_last) {
        // 1024 partials, 256 threads: 4 each in fixed order, then deterministic tree.
        float v = (g_part[t] + g_part[t + TPB])
                + (g_part[t + 2 * TPB] + g_part[t + 3 * TPB]);
        v = warp_sum(v);
        if (lane == 0) s_wred[warp] = v;
        __syncthreads();
        if (warp == 0) {
            float u = (lane < NWARP) ? s_wred[lane] : 0.0f;
            #pragma unroll
            for (int m = NWARP / 2; m > 0; m >>= 1)
                u += __shfl_xor_sync(0xFFFFFFFFu, u, m);
            if (lane == 0) {
                // final scale: LOSS_WEIGHT / (b*f*ns*nb) = 20 / 1568
                out[0] = u * (20.0f / 1568.0f);
            }
        }
    }
}

extern "C" void kernel_launch(void* const* d_in, const int* in_sizes, int n_in,
                              void* d_out, int out_size)
{
    (void)in_sizes; (void)n_in; (void)out_size;
    const float* seg  = (const float*)d_in[0];
    const float* mks  = (const float*)d_in[1];
    const float* rec  = (const float*)d_in[2];
    const float* tgt  = (const float*)d_in[3];
    const float* mvis = (const float*)d_in[4];
    const float* ai   = (const float*)d_in[5];
    float* out = (float*)d_out;

    loss_main<<<GRID, TPB>>>(seg, mks, rec, tgt, mvis, ai, out);
}